// round 6
// baseline (speedup 1.0000x reference)
#include <cuda_runtime.h>
#include <cuda_fp16.h>

// Problem constants: imgs [8,3,1024,1024] fp32, z [N,2] fp32, out [8,2] fp32
#define NY  1024
#define NX  1024
#define NB  8                // batches (channel-folded)
#define GBLOCK 256           // gather block: 64 points x 4 lanes
#define GPTS   64            // points per block per step
#define GATHER_BLOCKS 888    // 148 SMs * 6 resident blocks (occ-limited to 4)

// Scratch: channel-folded, fp16 pixel-major image Ph[y][x][b] (16 MiB, L2-resident)
__device__ __align__(128) __half g_Ph[(size_t)NY * NX * NB];
__device__ float g_partial[GATHER_BLOCKS * 16];

// ---------------------------------------------------------------------------
// Kernel 1: fold  imgs[b*3+c][y][x] --sum_c--> g_Ph[y][x][b] (fp16)
// Thread = pixel: 24 coalesced reads, one packed STG.128 of 8 halves.
// Traffic: 96MB read + 16MB write (was +32MB fp32).
// ---------------------------------------------------------------------------
__global__ void __launch_bounds__(128) fold_kernel(const float* __restrict__ imgs) {
    const int y = blockIdx.x >> 3;
    const int x = ((blockIdx.x & 7) << 7) + threadIdx.x;

    float s[NB];
    #pragma unroll
    for (int b = 0; b < NB; b++) {
        s[b] = 0.f;
        #pragma unroll
        for (int c = 0; c < 3; c++)
            s[b] += imgs[((size_t)(b * 3 + c) * NY + y) * NX + x];
    }
    __half2 h[4];
    #pragma unroll
    for (int k = 0; k < 4; k++)
        h[k] = __floats2half2_rn(s[2 * k], s[2 * k + 1]);
    *reinterpret_cast<uint4*>(g_Ph + ((size_t)y * NX + x) * NB) =
        *reinterpret_cast<const uint4*>(h);
}

// ---------------------------------------------------------------------------
// Per-point step: 4 lanes per point, lane q = (row = q&1, col = q>>1).
// Lane loads its tap's 8 fp16 batch values (16B); the quad's 4 taps span
// exactly 2 x 32B never-straddling line segments -> 2 L1tex lines/point (min).
// Signed coefficients (verified):
//   q=0 (r0,x):   c0=-w1x  c1=-w1y      q=1 (r1,x):   c0=+w1x  c1=+wyv
//   q=2 (r0,x+1): c0=+wxv  c1=+w1y      q=3 (r1,x+1): c0=-wxv  c1=-wyv
// i.e. c0 = s*(col? wxv:w1x), c1 = s*(row? wyv:w1y), s = (q==1||q==2)?+1:-1
// ---------------------------------------------------------------------------
__device__ __forceinline__ void proc_point(
    const float2* __restrict__ z2, const __half* __restrict__ Ph,
    int p, int row, int col, float s,
    float* __restrict__ a0, float* __restrict__ a1)
{
    float2 zz = __ldg(&z2[p]);
    float x0y = zz.x * 1023.0f;
    float x0x = zz.y * 1023.0f;
    bool oob = (x0y < 0.f) | (x0y > 1023.f) | (x0x < 0.f) | (x0x > 1023.f);
    if (oob) { x0y = 0.f; x0x = 0.f; }
    float ygf = floorf(x0y), xgf = floorf(x0x);
    int   yg = min((int)ygf, NY - 2);   // memory-safety clamp (never binds for z in [0,1))
    int   xg = min((int)xgf, NX - 2);
    float fy = ygf - x0y,  fx = xgf - x0x;     // in (-1, 0]
    float valid = oob ? 0.f : 1.f;
    float w1x = (1.f + fx) * valid, wxv = fx * valid;
    float w1y = (1.f + fy) * valid, wyv = fy * valid;

    float c0 = s * (col ? wxv : w1x);
    float c1 = s * (row ? wyv : w1y);

    int pix = (yg + row) * NX + (xg + col);
    uint4 raw = __ldg(reinterpret_cast<const uint4*>(Ph + (size_t)pix * NB));
    const __half2* hp = reinterpret_cast<const __half2*>(&raw);
    #pragma unroll
    for (int k = 0; k < 4; k++) {
        float2 f = __half22float2(hp[k]);
        a0[2*k]   = fmaf(c0, f.x, a0[2*k]);
        a0[2*k+1] = fmaf(c0, f.y, a0[2*k+1]);
        a1[2*k]   = fmaf(c1, f.x, a1[2*k]);
        a1[2*k+1] = fmaf(c1, f.y, a1[2*k+1]);
    }
}

// ---------------------------------------------------------------------------
// Kernel 2: fp16 gather. Warp = 8 points x 4 lanes; ONE warp-LDG.128 per
// point-iter covers all 32 taps (8 pts x 4 taps x 16B). Unroll x2 for MLP.
// Per-lane fp32 accumulators (8 batches x 2 outputs); deterministic reduce.
// ---------------------------------------------------------------------------
__global__ void __launch_bounds__(GBLOCK, 4) gather_kernel(const float* __restrict__ z, int n) {
    const int t    = threadIdx.x;
    const int q    = t & 3;
    const int row  = q & 1;
    const int col  = q >> 1;
    const float s  = ((q == 1) | (q == 2)) ? 1.f : -1.f;
    const int pl   = t >> 2;                        // point slot 0..63
    const int base = blockIdx.x * GPTS + pl;
    const int S    = gridDim.x * GPTS;

    const float2* __restrict__ z2 = reinterpret_cast<const float2*>(z);
    const __half* __restrict__ Ph = g_Ph;

    float a0[NB], a1[NB];
    #pragma unroll
    for (int k = 0; k < NB; k++) { a0[k] = 0.f; a1[k] = 0.f; }

    int p = base;
    for (; p + S < n; p += 2 * S) {
        proc_point(z2, Ph, p,     row, col, s, a0, a1);
        proc_point(z2, Ph, p + S, row, col, s, a0, a1);
    }
    for (; p < n; p += S)
        proc_point(z2, Ph, p, row, col, s, a0, a1);

    // Block reduction: 16 floats per thread -> 16KB smem, fixed order.
    __shared__ float sm[GBLOCK * 16];
    #pragma unroll
    for (int k = 0; k < NB; k++) {
        sm[t * 16 + k * 2    ] = a0[k];
        sm[t * 16 + k * 2 + 1] = a1[k];
    }
    __syncthreads();

    if (t < 16) {             // j = b*2 + o
        float sum = 0.f;
        #pragma unroll 8
        for (int tt = 0; tt < GBLOCK; tt++)
            sum += sm[tt * 16 + t];
        g_partial[blockIdx.x * 16 + t] = sum;
    }
}

// ---------------------------------------------------------------------------
// Kernel 3: deterministic final reduction of GATHER_BLOCKS x 16 partials.
// ---------------------------------------------------------------------------
__global__ void __launch_bounds__(256) reduce_kernel(float* __restrict__ out) {
    __shared__ float red[256];
    const int tid = threadIdx.x;
    const int j = tid & 15, g = tid >> 4;        // 16 outputs x 16 lanes each
    float sum = 0.f;
    for (int i = g; i < GATHER_BLOCKS; i += 16)
        sum += g_partial[i * 16 + j];
    red[tid] = sum;
    __syncthreads();
    if (tid < 16) {
        float s2 = 0.f;
        #pragma unroll
        for (int g2 = 0; g2 < 16; g2++)
            s2 += red[g2 * 16 + tid];
        out[tid] = s2;
    }
}

extern "C" void kernel_launch(void* const* d_in, const int* in_sizes, int n_in,
                              void* d_out, int out_size) {
    const float* imgs = (const float*)d_in[0];   // 8*3*1024*1024 fp32
    const float* z    = (const float*)d_in[1];   // N*2 fp32
    const int n_pts   = in_sizes[1] / 2;

    fold_kernel<<<NY * (NX / 128), 128>>>(imgs);
    gather_kernel<<<GATHER_BLOCKS, GBLOCK>>>(z, n_pts);
    reduce_kernel<<<1, 256>>>((float*)d_out);
}

// round 7
// speedup vs baseline: 1.0956x; 1.0956x over previous
#include <cuda_runtime.h>
#include <cuda_fp16.h>

// Problem constants: imgs [8,3,1024,1024] fp32, z [N,2] fp32, out [8,2] fp32
#define NY  1024
#define NX  1024
#define NB  8                // batches (channel-folded)
#define GBLOCK 256           // gather block: 64 points x 4 lanes
#define GPTS   64            // points per block per step
#define GATHER_BLOCKS 592    // 148 SMs * 4 resident = EXACTLY one wave

// Scratch: duplicated-row fp16 image R[y][x][16] = {P[y][x][0:8], P[y+1][x][0:8]}
// 32 MiB, L2-resident. All 4 bilinear taps of a point = 64B contiguous.
__device__ __align__(128) __half g_R[(size_t)NY * NX * 16];
__device__ float g_partial[GATHER_BLOCKS * 16];

// ---------------------------------------------------------------------------
// Kernel 1: fold  imgs[b*3+c][y][x] --sum_c--> fp16, written twice:
//   R[y][x][0:8]    (as "row y" of group y)
//   R[y-1][x][8:16] (as "row y+1" of group y-1), skipped for y=0.
// R[1023][x][8:16] is never read (yg <= 1022) so it stays unwritten.
// Traffic: 96MB read + 32MB write.
// ---------------------------------------------------------------------------
__global__ void __launch_bounds__(128) fold_kernel(const float* __restrict__ imgs) {
    const int y = blockIdx.x >> 3;
    const int x = ((blockIdx.x & 7) << 7) + threadIdx.x;

    float s[NB];
    #pragma unroll
    for (int b = 0; b < NB; b++) {
        s[b] = 0.f;
        #pragma unroll
        for (int c = 0; c < 3; c++)
            s[b] += imgs[((size_t)(b * 3 + c) * NY + y) * NX + x];
    }
    __half2 h[4];
    #pragma unroll
    for (int k = 0; k < 4; k++)
        h[k] = __floats2half2_rn(s[2 * k], s[2 * k + 1]);
    const uint4 v = *reinterpret_cast<const uint4*>(h);

    *reinterpret_cast<uint4*>(g_R + ((size_t)y * NX + x) * 16) = v;
    if (y > 0)
        *reinterpret_cast<uint4*>(g_R + ((size_t)(y - 1) * NX + x) * 16 + 8) = v;
}

// ---------------------------------------------------------------------------
// Per-point step: 4 lanes per point, lane q -> (row = q&1, col = q>>1).
// Lane loads 16B at R[(yg)*NX + xg + col] + (q&1)*8 halves; the quad's 4 taps
// are ONE contiguous 64B span (1.25 L1tex lines/point avg).
// Signed coefficients (same derivation as R4/R5):
//   c0 = s*(col? wxv:w1x), c1 = s*(row? wyv:w1y), s = (q==1||q==2)?+1:-1
// ---------------------------------------------------------------------------
__device__ __forceinline__ void proc_point(
    const float2* __restrict__ z2, const __half* __restrict__ R,
    int p, int row, int col, float s,
    float* __restrict__ a0, float* __restrict__ a1)
{
    float2 zz = __ldg(&z2[p]);
    float x0y = zz.x * 1023.0f;
    float x0x = zz.y * 1023.0f;
    bool oob = (x0y < 0.f) | (x0y > 1023.f) | (x0x < 0.f) | (x0x > 1023.f);
    if (oob) { x0y = 0.f; x0x = 0.f; }
    float ygf = floorf(x0y), xgf = floorf(x0x);
    int   yg = min((int)ygf, NY - 2);   // safety clamp (never binds for z in [0,1))
    int   xg = min((int)xgf, NX - 2);
    float fy = ygf - x0y,  fx = xgf - x0x;     // in (-1, 0]
    float valid = oob ? 0.f : 1.f;
    float w1x = (1.f + fx) * valid, wxv = fx * valid;
    float w1y = (1.f + fy) * valid, wyv = fy * valid;

    float c0 = s * (col ? wxv : w1x);
    float c1 = s * (row ? wyv : w1y);

    size_t base = ((size_t)yg * NX + (xg + col)) * 16 + row * 8;
    uint4 raw = __ldg(reinterpret_cast<const uint4*>(R + base));
    const __half2* hp = reinterpret_cast<const __half2*>(&raw);
    #pragma unroll
    for (int k = 0; k < 4; k++) {
        float2 f = __half22float2(hp[k]);
        a0[2*k]   = fmaf(c0, f.x, a0[2*k]);
        a0[2*k+1] = fmaf(c0, f.y, a0[2*k+1]);
        a1[2*k]   = fmaf(c1, f.x, a1[2*k]);
        a1[2*k+1] = fmaf(c1, f.y, a1[2*k+1]);
    }
}

// ---------------------------------------------------------------------------
// Kernel 2: single-wave fp16 gather over duplicated-row layout.
// Warp = 8 points x 4 lanes; one LDG.128/lane/point; ~10 lines per warp-LDG
// (8 x 1.25). Unroll x2 for MLP. Deterministic fixed-order reduction.
// ---------------------------------------------------------------------------
__global__ void __launch_bounds__(GBLOCK, 4) gather_kernel(const float* __restrict__ z, int n) {
    const int t    = threadIdx.x;
    const int q    = t & 3;
    const int row  = q & 1;
    const int col  = q >> 1;
    const float s  = ((q == 1) | (q == 2)) ? 1.f : -1.f;
    const int pl   = t >> 2;                        // point slot 0..63
    const int base = blockIdx.x * GPTS + pl;
    const int S    = gridDim.x * GPTS;

    const float2* __restrict__ z2 = reinterpret_cast<const float2*>(z);
    const __half* __restrict__ R  = g_R;

    float a0[NB], a1[NB];
    #pragma unroll
    for (int k = 0; k < NB; k++) { a0[k] = 0.f; a1[k] = 0.f; }

    int p = base;
    for (; p + S < n; p += 2 * S) {
        proc_point(z2, R, p,     row, col, s, a0, a1);
        proc_point(z2, R, p + S, row, col, s, a0, a1);
    }
    for (; p < n; p += S)
        proc_point(z2, R, p, row, col, s, a0, a1);

    // Block reduction: 16 floats per thread -> 16KB smem, fixed order.
    __shared__ float sm[GBLOCK * 16];
    #pragma unroll
    for (int k = 0; k < NB; k++) {
        sm[t * 16 + k * 2    ] = a0[k];
        sm[t * 16 + k * 2 + 1] = a1[k];
    }
    __syncthreads();

    if (t < 16) {             // j = b*2 + o
        float sum = 0.f;
        #pragma unroll 8
        for (int tt = 0; tt < GBLOCK; tt++)
            sum += sm[tt * 16 + t];
        g_partial[blockIdx.x * 16 + t] = sum;
    }
}

// ---------------------------------------------------------------------------
// Kernel 3: deterministic final reduction of GATHER_BLOCKS x 16 partials.
// ---------------------------------------------------------------------------
__global__ void __launch_bounds__(256) reduce_kernel(float* __restrict__ out) {
    __shared__ float red[256];
    const int tid = threadIdx.x;
    const int j = tid & 15, g = tid >> 4;        // 16 outputs x 16 lanes each
    float sum = 0.f;
    for (int i = g; i < GATHER_BLOCKS; i += 16)
        sum += g_partial[i * 16 + j];
    red[tid] = sum;
    __syncthreads();
    if (tid < 16) {
        float s2 = 0.f;
        #pragma unroll
        for (int g2 = 0; g2 < 16; g2++)
            s2 += red[g2 * 16 + tid];
        out[tid] = s2;
    }
}

extern "C" void kernel_launch(void* const* d_in, const int* in_sizes, int n_in,
                              void* d_out, int out_size) {
    const float* imgs = (const float*)d_in[0];   // 8*3*1024*1024 fp32
    const float* z    = (const float*)d_in[1];   // N*2 fp32
    const int n_pts   = in_sizes[1] / 2;

    fold_kernel<<<NY * (NX / 128), 128>>>(imgs);
    gather_kernel<<<GATHER_BLOCKS, GBLOCK>>>(z, n_pts);
    reduce_kernel<<<1, 256>>>((float*)d_out);
}

// round 8
// speedup vs baseline: 1.1992x; 1.0946x over previous
#include <cuda_runtime.h>
#include <cuda_fp16.h>

// Problem constants: imgs [8,3,1024,1024] fp32, z [N,2] fp32, out [8,2] fp32
#define NY  1024
#define NX  1024
#define NB  8                // batches (channel-folded)
#define GBLOCK 256           // gather block: 64 points x 4 lanes
#define GPTS   64            // points per block per step
#define GATHER_BLOCKS 592    // 148 SMs * 4 resident = EXACTLY one wave

// Scratch: duplicated-row fp16 image R[y][x][16] = {P[y][x][0:8], P[y+1][x][0:8]}
// 32 MiB, L2-resident. All 4 bilinear taps of a point = 64B contiguous.
__device__ __align__(128) __half g_R[(size_t)NY * NX * 16];
__device__ float g_partial[GATHER_BLOCKS * 16];

// ---------------------------------------------------------------------------
// Kernel 1: fold  imgs[b*3+c][y][x] --sum_c--> fp16, written twice:
//   R[y][x][0:8]  and  R[y-1][x][8:16]  (frozen from R6: 22.2us, DRAM 63%)
// ---------------------------------------------------------------------------
__global__ void __launch_bounds__(128) fold_kernel(const float* __restrict__ imgs) {
    const int y = blockIdx.x >> 3;
    const int x = ((blockIdx.x & 7) << 7) + threadIdx.x;

    float s[NB];
    #pragma unroll
    for (int b = 0; b < NB; b++) {
        s[b] = 0.f;
        #pragma unroll
        for (int c = 0; c < 3; c++)
            s[b] += imgs[((size_t)(b * 3 + c) * NY + y) * NX + x];
    }
    __half2 h[4];
    #pragma unroll
    for (int k = 0; k < 4; k++)
        h[k] = __floats2half2_rn(s[2 * k], s[2 * k + 1]);
    const uint4 v = *reinterpret_cast<const uint4*>(h);

    *reinterpret_cast<uint4*>(g_R + ((size_t)y * NX + x) * 16) = v;
    if (y > 0)
        *reinterpret_cast<uint4*>(g_R + ((size_t)(y - 1) * NX + x) * 16 + 8) = v;
}

// ---------------------------------------------------------------------------
// Weight/address computation for one point (lane view).
//   c0 = s*(col? wxv:w1x), c1 = s*(row? wyv:w1y), s = (q==1||q==2)?+1:-1
// ---------------------------------------------------------------------------
__device__ __forceinline__ void point_setup(
    float2 zz, int row, int col, float s,
    float& c0, float& c1, size_t& addr)
{
    float x0y = zz.x * 1023.0f;
    float x0x = zz.y * 1023.0f;
    bool oob = (x0y < 0.f) | (x0y > 1023.f) | (x0x < 0.f) | (x0x > 1023.f);
    if (oob) { x0y = 0.f; x0x = 0.f; }
    float ygf = floorf(x0y), xgf = floorf(x0x);
    int   yg = min((int)ygf, NY - 2);   // safety clamp (never binds for z in [0,1))
    int   xg = min((int)xgf, NX - 2);
    float fy = ygf - x0y,  fx = xgf - x0x;     // in (-1, 0]
    float valid = oob ? 0.f : 1.f;
    float w1x = (1.f + fx) * valid, wxv = fx * valid;
    float w1y = (1.f + fy) * valid, wyv = fy * valid;
    c0 = s * (col ? wxv : w1x);
    c1 = s * (row ? wyv : w1y);
    addr = ((size_t)yg * NX + (xg + col)) * 16 + row * 8;
}

__device__ __forceinline__ void accum(
    uint4 raw, float c0, float c1,
    float* __restrict__ a0, float* __restrict__ a1)
{
    const __half2* hp = reinterpret_cast<const __half2*>(&raw);
    #pragma unroll
    for (int k = 0; k < 4; k++) {
        float2 f = __half22float2(hp[k]);
        a0[2*k]   = fmaf(c0, f.x, a0[2*k]);
        a0[2*k+1] = fmaf(c0, f.y, a0[2*k+1]);
        a1[2*k]   = fmaf(c1, f.x, a1[2*k]);
        a1[2*k+1] = fmaf(c1, f.y, a1[2*k+1]);
    }
}

// ---------------------------------------------------------------------------
// Kernel 2: software-pipelined fp16 gather (unroll x4): batch 4 z-loads, then
// 4 tap-loads, then accumulate -> 4 outstanding taps/thread to cover L2+queue
// latency. Warp = 8 points x 4 lanes, one LDG.128/lane/point. Deterministic.
// ---------------------------------------------------------------------------
__global__ void __launch_bounds__(GBLOCK, 4) gather_kernel(const float* __restrict__ z, int n) {
    const int t    = threadIdx.x;
    const int q    = t & 3;
    const int row  = q & 1;
    const int col  = q >> 1;
    const float s  = ((q == 1) | (q == 2)) ? 1.f : -1.f;
    const int pl   = t >> 2;                        // point slot 0..63
    const int base = blockIdx.x * GPTS + pl;
    const int S    = gridDim.x * GPTS;

    const float2* __restrict__ z2 = reinterpret_cast<const float2*>(z);
    const __half* __restrict__ R  = g_R;

    float a0[NB], a1[NB];
    #pragma unroll
    for (int k = 0; k < NB; k++) { a0[k] = 0.f; a1[k] = 0.f; }

    int p = base;
    for (; p + 3 * S < n; p += 4 * S) {
        float2 zz[4];
        #pragma unroll
        for (int k = 0; k < 4; k++)
            zz[k] = __ldg(&z2[p + k * S]);          // 4 independent z-loads

        float c0[4], c1[4];
        size_t addr[4];
        uint4 raw[4];
        #pragma unroll
        for (int k = 0; k < 4; k++) {
            point_setup(zz[k], row, col, s, c0[k], c1[k], addr[k]);
            raw[k] = __ldg(reinterpret_cast<const uint4*>(R + addr[k]));
        }
        #pragma unroll
        for (int k = 0; k < 4; k++)
            accum(raw[k], c0[k], c1[k], a0, a1);
    }
    for (; p < n; p += S) {
        float2 zz = __ldg(&z2[p]);
        float c0, c1; size_t addr;
        point_setup(zz, row, col, s, c0, c1, addr);
        uint4 raw = __ldg(reinterpret_cast<const uint4*>(R + addr));
        accum(raw, c0, c1, a0, a1);
    }

    // Block reduction: 16 floats per thread -> 16KB smem, fixed order.
    __shared__ float sm[GBLOCK * 16];
    #pragma unroll
    for (int k = 0; k < NB; k++) {
        sm[t * 16 + k * 2    ] = a0[k];
        sm[t * 16 + k * 2 + 1] = a1[k];
    }
    __syncthreads();

    if (t < 16) {             // j = b*2 + o
        float sum = 0.f;
        #pragma unroll 8
        for (int tt = 0; tt < GBLOCK; tt++)
            sum += sm[tt * 16 + t];
        g_partial[blockIdx.x * 16 + t] = sum;
    }
}

// ---------------------------------------------------------------------------
// Kernel 3: deterministic final reduction of GATHER_BLOCKS x 16 partials.
// ---------------------------------------------------------------------------
__global__ void __launch_bounds__(256) reduce_kernel(float* __restrict__ out) {
    __shared__ float red[256];
    const int tid = threadIdx.x;
    const int j = tid & 15, g = tid >> 4;        // 16 outputs x 16 lanes each
    float sum = 0.f;
    for (int i = g; i < GATHER_BLOCKS; i += 16)
        sum += g_partial[i * 16 + j];
    red[tid] = sum;
    __syncthreads();
    if (tid < 16) {
        float s2 = 0.f;
        #pragma unroll
        for (int g2 = 0; g2 < 16; g2++)
            s2 += red[g2 * 16 + tid];
        out[tid] = s2;
    }
}

extern "C" void kernel_launch(void* const* d_in, const int* in_sizes, int n_in,
                              void* d_out, int out_size) {
    const float* imgs = (const float*)d_in[0];   // 8*3*1024*1024 fp32
    const float* z    = (const float*)d_in[1];   // N*2 fp32
    const int n_pts   = in_sizes[1] / 2;

    fold_kernel<<<NY * (NX / 128), 128>>>(imgs);
    gather_kernel<<<GATHER_BLOCKS, GBLOCK>>>(z, n_pts);
    reduce_kernel<<<1, 256>>>((float*)d_out);
}